// round 5
// baseline (speedup 1.0000x reference)
#include <cuda_runtime.h>
#include <cstdint>

#define D_MODEL 1024
#define NB 4
#define NCHAIN 8              // (batch, parity) chains
#define NCTA 128
#define NTHREADS 256          // 8 warps, one row per warp
#define BOS 0

// Persistent cross-kernel state (static __device__: no allocation).
__device__ float                  g_W2[D_MODEL * D_MODEL];     // W @ W
__device__ float                  g_hbuf[2][NCHAIN][D_MODEL];  // slot = k & 1
__device__ __align__(16) unsigned g_tag[NCHAIN * NCTA];        // tag=k+1 => H_k visible

__global__ void rnn_init_kernel() {
    int i = blockIdx.x * blockDim.x + threadIdx.x;
    if (i < NCHAIN * NCTA) g_tag[i] = 0u;
    if (i < 2 * NCHAIN * D_MODEL) reinterpret_cast<float*>(g_hbuf)[i] = 0.0f;
}

__device__ __forceinline__ uint4 ld_acquire_v4(const uint4* p) {
    uint4 v;
    asm volatile("ld.acquire.gpu.global.v4.u32 {%0,%1,%2,%3}, [%4];"
                 : "=r"(v.x), "=r"(v.y), "=r"(v.z), "=r"(v.w) : "l"(p) : "memory");
    return v;
}
__device__ __forceinline__ void st_release_u32(unsigned* p, unsigned v) {
    asm volatile("st.release.gpu.global.u32 [%0], %1;" :: "l"(p), "r"(v) : "memory");
}

// ---------------------------------------------------------------------------
// Kernel A: g_W2 = W @ W   (fp32 tiled GEMM, 64x64 tiles, K-chunks of 32)
// ---------------------------------------------------------------------------
__global__ void __launch_bounds__(256, 1)
w2_gemm_kernel(const float* __restrict__ W) {
    __shared__ float As[32][68];   // As[k][m] (A transposed on load)
    __shared__ float Bs[32][68];   // Bs[k][n]

    const int tid = threadIdx.x;
    const int tx = tid & 15, ty = tid >> 4;
    const int ii = blockIdx.y * 64, jj = blockIdx.x * 64;

    float acc[4][4] = {};
    for (int kk = 0; kk < D_MODEL; kk += 32) {
        // A = W[ii..ii+63][kk..kk+31], stored transposed As[k][m]
        {
            int r = tid >> 3;                 // 0..31
            int c4 = (tid & 7) * 4;           // 0..28
#pragma unroll
            for (int h = 0; h < 2; ++h) {
                int m = r + 32 * h;
                float4 av = *(const float4*)&W[(size_t)(ii + m) * D_MODEL + kk + c4];
                As[c4 + 0][m] = av.x; As[c4 + 1][m] = av.y;
                As[c4 + 2][m] = av.z; As[c4 + 3][m] = av.w;
            }
        }
        // B = W[kk..kk+31][jj..jj+63], direct Bs[k][n]
        {
            int k0 = tid >> 4;                // 0..15
            int f4 = (tid & 15) * 4;
            *(float4*)&Bs[k0][f4] =
                *(const float4*)&W[(size_t)(kk + k0) * D_MODEL + jj + f4];
            *(float4*)&Bs[k0 + 16][f4] =
                *(const float4*)&W[(size_t)(kk + k0 + 16) * D_MODEL + jj + f4];
        }
        __syncthreads();
#pragma unroll
        for (int k = 0; k < 32; ++k) {
            float4 a = *(const float4*)&As[k][ty * 4];
            float4 b = *(const float4*)&Bs[k][tx * 4];
            acc[0][0] += a.x * b.x; acc[0][1] += a.x * b.y; acc[0][2] += a.x * b.z; acc[0][3] += a.x * b.w;
            acc[1][0] += a.y * b.x; acc[1][1] += a.y * b.y; acc[1][2] += a.y * b.z; acc[1][3] += a.y * b.w;
            acc[2][0] += a.z * b.x; acc[2][1] += a.z * b.y; acc[2][2] += a.z * b.z; acc[2][3] += a.z * b.w;
            acc[3][0] += a.w * b.x; acc[3][1] += a.w * b.y; acc[3][2] += a.w * b.z; acc[3][3] += a.w * b.w;
        }
        __syncthreads();
    }
#pragma unroll
    for (int r = 0; r < 4; ++r) {
        float4 v = make_float4(acc[r][0], acc[r][1], acc[r][2], acc[r][3]);
        *(float4*)&g_W2[(size_t)(ii + ty * 4 + r) * D_MODEL + jj + tx * 4] = v;
    }
}

// ---------------------------------------------------------------------------
// Kernel B: out[b,t,:] = y_t = emb[tok_t] + W @ emb[tok_{t-1}]   (y_0 = x_0)
// M = NB*Tp1 rows. Pure parallel GEMM with embedding gather.
// ---------------------------------------------------------------------------
__global__ void __launch_bounds__(256, 1)
y_gemm_kernel(const int* __restrict__ ids, const float* __restrict__ emb,
              const float* __restrict__ W, float* __restrict__ out, int Tp1) {
    __shared__ float As[32][68];   // As[k][m] = x_prev[m][k]
    __shared__ float Bs[32][68];   // Bs[k][n] = W[n][k]

    const int tid = threadIdx.x;
    const int tx = tid & 15, ty = tid >> 4;
    const int ii = blockIdx.x * 64, jj = blockIdx.y * 64;
    const int M = NB * Tp1;
    const int T = Tp1 - 1;

    // Per-loader row pointers for the A gather (2 rows per thread).
    const int lr = tid >> 3;            // 0..31
    const int lc4 = (tid & 7) * 4;
    const float* arow[2];
#pragma unroll
    for (int h = 0; h < 2; ++h) {
        int m = ii + lr + 32 * h;
        arow[h] = nullptr;
        if (m < M) {
            int b = m / Tp1, t = m - b * Tp1;
            if (t > 0) {
                int tprev = t - 1;
                int tok = (tprev == 0) ? BOS : ids[b * T + tprev - 1];
                arow[h] = emb + (size_t)tok * D_MODEL;
            }
        }
    }

    float acc[4][4] = {};
    for (int kk = 0; kk < D_MODEL; kk += 32) {
#pragma unroll
        for (int h = 0; h < 2; ++h) {
            int m = lr + 32 * h;
            float4 av = arow[h] ? *(const float4*)&arow[h][kk + lc4]
                                : make_float4(0.f, 0.f, 0.f, 0.f);
            As[lc4 + 0][m] = av.x; As[lc4 + 1][m] = av.y;
            As[lc4 + 2][m] = av.z; As[lc4 + 3][m] = av.w;
        }
        {   // Bs[k][n] = W[jj+n][kk+k] (transpose on load)
            int n = tid >> 3;               // 0..31
            int kf4 = (tid & 7) * 4;
#pragma unroll
            for (int h = 0; h < 2; ++h) {
                int nn = n + 32 * h;
                float4 bv = *(const float4*)&W[(size_t)(jj + nn) * D_MODEL + kk + kf4];
                Bs[kf4 + 0][nn] = bv.x; Bs[kf4 + 1][nn] = bv.y;
                Bs[kf4 + 2][nn] = bv.z; Bs[kf4 + 3][nn] = bv.w;
            }
        }
        __syncthreads();
#pragma unroll
        for (int k = 0; k < 32; ++k) {
            float4 a = *(const float4*)&As[k][ty * 4];
            float4 b = *(const float4*)&Bs[k][tx * 4];
            acc[0][0] += a.x * b.x; acc[0][1] += a.x * b.y; acc[0][2] += a.x * b.z; acc[0][3] += a.x * b.w;
            acc[1][0] += a.y * b.x; acc[1][1] += a.y * b.y; acc[1][2] += a.y * b.z; acc[1][3] += a.y * b.w;
            acc[2][0] += a.z * b.x; acc[2][1] += a.z * b.y; acc[2][2] += a.z * b.z; acc[2][3] += a.z * b.w;
            acc[3][0] += a.w * b.x; acc[3][1] += a.w * b.y; acc[3][2] += a.w * b.z; acc[3][3] += a.w * b.w;
        }
        __syncthreads();
    }
#pragma unroll
    for (int r = 0; r < 4; ++r) {
        int m = ii + ty * 4 + r;
        if (m < M) {
            int b = m / Tp1, t = m - b * Tp1;
            int tok = (t == 0) ? BOS : ids[b * T + t - 1];
            float4 e = *(const float4*)&emb[(size_t)tok * D_MODEL + jj + tx * 4];
            float4 v = make_float4(acc[r][0] + e.x, acc[r][1] + e.y,
                                   acc[r][2] + e.z, acc[r][3] + e.w);
            *(float4*)&out[(size_t)m * D_MODEL + jj + tx * 4] = v;
        }
    }
}

// ---------------------------------------------------------------------------
// Kernel C: persistent scan over 8 chains: H_k = y + W2 @ H_{k-1}
// chain c = (b, p): H_k == h_{2k+p} of batch b. Dependency distance 8 units.
// ---------------------------------------------------------------------------
__global__ void __launch_bounds__(NTHREADS, 1)
rnn_scan_kernel(float* __restrict__ out, int Tp1) {
    __shared__ float4 hsm[2][D_MODEL / 4];

    const int tid  = threadIdx.x;
    const int w    = tid >> 5;
    const int lane = tid & 31;
    const int row  = blockIdx.x * 8 + w;

    // W2 row -> registers
    const float4* __restrict__ Wv = reinterpret_cast<const float4*>(g_W2);
    float4 wr[8];
#pragma unroll
    for (int k = 0; k < 8; ++k) wr[k] = Wv[(size_t)row * 256 + lane + 32 * k];

    hsm[0][tid] = make_float4(0.f, 0.f, 0.f, 0.f);   // H_{-1} = 0 for unit 0
    __syncthreads();

    const float4* hbufv = reinterpret_cast<const float4*>(g_hbuf); // [2][8][256]
    const int KMAX = (Tp1 + 1) >> 1;
    const unsigned nunits = (unsigned)KMAX * NCHAIN;

    for (unsigned u = 0; u < nunits; ++u) {
        const int k = (int)(u >> 3);
        const int c = (int)(u & 7);
        const int b = c >> 1, p = c & 1;
        const int t = 2 * k + p;
        const int q = (int)(u & 1);
        const bool valid = (t < Tp1);

        // ---- A. issue tag probe for unit u+6's input (warp 7, split txn) ----
        const unsigned u2 = u + 6;
        uint4 probe = make_uint4(~0u, ~0u, ~0u, ~0u);
        const uint4* tagp = nullptr;
        unsigned need = 0;
        if (w == 7 && u2 < nunits) {
            const int k6 = (int)(u2 >> 3), c6 = (int)(u2 & 7);
            if (k6 > 0) {
                tagp = reinterpret_cast<const uint4*>(g_tag + c6 * NCTA) + lane;
                need = (unsigned)k6;
                probe = ld_acquire_v4(tagp);
            }
        }

        // ---- B. issue h-stage load for unit u+1 (availability confirmed u-5) ----
        const unsigned un = u + 1;
        const bool have_next = (un < nunits);
        float4 hstage;
        if (have_next) {
            const int kn = (int)(un >> 3), cn = (int)(un & 7);
            const int slot = (kn + 1) & 1;               // H_{kn-1} lives here
            hstage = __ldcg(&hbufv[((size_t)slot * NCHAIN + cn) * 256 + tid]);
        }

        // ---- y read for this unit (split txn, lane 0) ----
        float yv = 0.0f;
        size_t oidx = 0;
        if (lane == 0 && valid) {
            oidx = ((size_t)b * Tp1 + t) * D_MODEL + row;
            yv = __ldcg(&out[oidx]);
        }

        // ---- C. matvec: full row per warp, 4 accumulators ----
        const float4* __restrict__ h4 = hsm[q];
        float a0 = 0.f, a1 = 0.f, a2 = 0.f, a3 = 0.f;
#pragma unroll
        for (int kk = 0; kk < 8; kk += 4) {
            float4 h0 = h4[lane + 32 * (kk + 0)];
            float4 h1 = h4[lane + 32 * (kk + 1)];
            float4 h2 = h4[lane + 32 * (kk + 2)];
            float4 h3 = h4[lane + 32 * (kk + 3)];
            a0 += wr[kk + 0].x * h0.x; a0 += wr[kk + 0].y * h0.y;
            a0 += wr[kk + 0].z * h0.z; a0 += wr[kk + 0].w * h0.w;
            a1 += wr[kk + 1].x * h1.x; a1 += wr[kk + 1].y * h1.y;
            a1 += wr[kk + 1].z * h1.z; a1 += wr[kk + 1].w * h1.w;
            a2 += wr[kk + 2].x * h2.x; a2 += wr[kk + 2].y * h2.y;
            a2 += wr[kk + 2].z * h2.z; a2 += wr[kk + 2].w * h2.w;
            a3 += wr[kk + 3].x * h3.x; a3 += wr[kk + 3].y * h3.y;
            a3 += wr[kk + 3].z * h3.z; a3 += wr[kk + 3].w * h3.w;
        }
        float a = (a0 + a1) + (a2 + a3);
#pragma unroll
        for (int off = 16; off > 0; off >>= 1)
            a += __shfl_xor_sync(0xffffffffu, a, off);

        // ---- D. epilogue: H_k = y + W2 H_{k-1}; publish to gmem ----
        if (lane == 0 && valid) {
            float v = a + yv;
            __stcg(&g_hbuf[k & 1][c][row], v);
            out[oidx] = v;                       // overwrite y with h
        }

        // ---- E. publish stage into the other smem buffer ----
        if (have_next) hsm[q ^ 1][tid] = hstage;

        // ---- F. check probe; retry only on a genuine miss ----
        if (tagp) {
            unsigned m = min(min(probe.x, probe.y), min(probe.z, probe.w));
            while (!__all_sync(0xffffffffu, m >= need)) {
                uint4 v = ld_acquire_v4(tagp);
                m = min(min(v.x, v.y), min(v.z, v.w));
            }
        }

        // ---- G. single barrier; H. release tag ----
        __syncthreads();
        if (tid == 0) st_release_u32(&g_tag[c * NCTA + blockIdx.x], (unsigned)(k + 1));
    }
}

extern "C" void kernel_launch(void* const* d_in, const int* in_sizes, int n_in,
                              void* d_out, int out_size) {
    const int*   ids = (const int*)d_in[0];
    const float* emb = (const float*)d_in[1];
    const float* W   = (const float*)d_in[2];
    float* out = (float*)d_out;

    int Tp1 = out_size / (NB * D_MODEL);   // 2049 for the reference shapes
    int M = NB * Tp1;

    rnn_init_kernel<<<64, 256>>>();
    w2_gemm_kernel<<<dim3(16, 16), 256>>>(W);
    y_gemm_kernel<<<dim3((M + 63) / 64, 16), 256>>>(ids, emb, W, out, Tp1);
    rnn_scan_kernel<<<NCTA, NTHREADS>>>(out, Tp1);
}

// round 6
// speedup vs baseline: 1.2033x; 1.2033x over previous
#include <cuda_runtime.h>
#include <cstdint>

#define D_MODEL 1024
#define NB 4
#define NCHAIN 8              // (batch, parity) chains
#define NCTA 128
#define NTHREADS 256          // 8 warps, one row per warp
#define BOS 0

// Persistent cross-kernel state (static __device__: no allocation).
__device__ float                  g_W2[D_MODEL * D_MODEL];     // W @ W
__device__ float                  g_hbuf[2][NCHAIN][D_MODEL];  // slot = k & 1
__device__ __align__(16) unsigned g_tag[NCHAIN * NCTA];        // tag=k+1 => H_k visible

__global__ void rnn_init_kernel() {
    int i = blockIdx.x * blockDim.x + threadIdx.x;
    if (i < NCHAIN * NCTA) g_tag[i] = 0u;
    if (i < 2 * NCHAIN * D_MODEL) reinterpret_cast<float*>(g_hbuf)[i] = 0.0f;
}

__device__ __forceinline__ uint4 ld_acquire_v4(const uint4* p) {
    uint4 v;
    asm volatile("ld.acquire.gpu.global.v4.u32 {%0,%1,%2,%3}, [%4];"
                 : "=r"(v.x), "=r"(v.y), "=r"(v.z), "=r"(v.w) : "l"(p) : "memory");
    return v;
}
__device__ __forceinline__ void st_release_u32(unsigned* p, unsigned v) {
    asm volatile("st.release.gpu.global.u32 [%0], %1;" :: "l"(p), "r"(v) : "memory");
}

// ---------------------------------------------------------------------------
// Kernel A: g_W2 = W @ W.  128x128x16 SGEMM, 256 threads, 8x8/thread.
//   c[i][j] = sum_k W[i][k] * W[k][j]  -> A rows direct, B rows direct.
// ---------------------------------------------------------------------------
__global__ void __launch_bounds__(256, 1)
w2_gemm_kernel(const float* __restrict__ W) {
    __shared__ float As[16][132];   // As[k][m]
    __shared__ float Bs[16][132];   // Bs[k][n]

    const int tid = threadIdx.x;
    const int tx = tid & 15, ty = tid >> 4;
    const int ii = blockIdx.y * 128, jj = blockIdx.x * 128;

    // A loader: row ar (+64), k-cols ac4..ac4+3 (transpose into As)
    const int ar = tid >> 2, ac4 = (tid & 3) * 4;
    // B loader: k-row br (+8), n-cols bc4..bc4+3 (direct into Bs)
    const int br = tid >> 5, bc4 = (tid & 31) * 4;

    float acc[8][8] = {};
    for (int kk = 0; kk < D_MODEL; kk += 16) {
#pragma unroll
        for (int h = 0; h < 2; ++h) {
            int m = ar + 64 * h;
            float4 av = *(const float4*)&W[(size_t)(ii + m) * D_MODEL + kk + ac4];
            As[ac4 + 0][m] = av.x; As[ac4 + 1][m] = av.y;
            As[ac4 + 2][m] = av.z; As[ac4 + 3][m] = av.w;
        }
#pragma unroll
        for (int h = 0; h < 2; ++h) {
            int k = br + 8 * h;
            *(float4*)&Bs[k][bc4] =
                *(const float4*)&W[(size_t)(kk + k) * D_MODEL + jj + bc4];
        }
        __syncthreads();
#pragma unroll
        for (int k = 0; k < 16; ++k) {
            float a[8], b[8];
            *(float4*)&a[0] = *(const float4*)&As[k][ty * 8];
            *(float4*)&a[4] = *(const float4*)&As[k][ty * 8 + 4];
            *(float4*)&b[0] = *(const float4*)&Bs[k][tx * 8];
            *(float4*)&b[4] = *(const float4*)&Bs[k][tx * 8 + 4];
#pragma unroll
            for (int i = 0; i < 8; ++i)
#pragma unroll
                for (int j = 0; j < 8; ++j)
                    acc[i][j] += a[i] * b[j];
        }
        __syncthreads();
    }
#pragma unroll
    for (int i = 0; i < 8; ++i) {
        float* dst = &g_W2[(size_t)(ii + ty * 8 + i) * D_MODEL + jj + tx * 8];
        *(float4*)&dst[0] = make_float4(acc[i][0], acc[i][1], acc[i][2], acc[i][3]);
        *(float4*)&dst[4] = make_float4(acc[i][4], acc[i][5], acc[i][6], acc[i][7]);
    }
}

// ---------------------------------------------------------------------------
// Kernel B: out[m,:] = y = emb[tok_t] + W @ emb[tok_{t-1}]   (y_0 = x_0)
//   C = A @ W^T with A rows gathered from emb. 128x128x16 SGEMM.
// ---------------------------------------------------------------------------
__global__ void __launch_bounds__(256, 1)
y_gemm_kernel(const int* __restrict__ ids, const float* __restrict__ emb,
              const float* __restrict__ W, float* __restrict__ out, int Tp1) {
    __shared__ float As[16][132];   // As[k][m] = x_prev[m][k]
    __shared__ float Bs[16][132];   // Bs[k][n] = W[n][k] (transposed on load)

    const int tid = threadIdx.x;
    const int tx = tid & 15, ty = tid >> 4;
    const int ii = blockIdx.y * 128, jj = blockIdx.x * 128;
    const int M = NB * Tp1;
    const int T = Tp1 - 1;

    // A loader: gathered emb row pointers for rows ii+ar, ii+ar+64
    const int ar = tid >> 2, ac4 = (tid & 3) * 4;
    const float* arow[2];
#pragma unroll
    for (int h = 0; h < 2; ++h) {
        int m = ii + ar + 64 * h;
        arow[h] = nullptr;
        if (m < M) {
            int b = m / Tp1, t = m - b * Tp1;
            if (t > 0) {
                int tok = (t == 1) ? BOS : ids[b * T + t - 2];
                arow[h] = emb + (size_t)tok * D_MODEL;
            }
        }
    }
    // B loader: W[jj+bn][k] -> Bs[k][bn], 8 floats along k per thread
    const int bn = tid >> 1, bk8 = (tid & 1) * 8;

    float acc[8][8] = {};
    for (int kk = 0; kk < D_MODEL; kk += 16) {
#pragma unroll
        for (int h = 0; h < 2; ++h) {
            float4 av = arow[h] ? *(const float4*)&arow[h][kk + ac4]
                                : make_float4(0.f, 0.f, 0.f, 0.f);
            int m = ar + 64 * h;
            As[ac4 + 0][m] = av.x; As[ac4 + 1][m] = av.y;
            As[ac4 + 2][m] = av.z; As[ac4 + 3][m] = av.w;
        }
        {
            float4 b0 = *(const float4*)&W[(size_t)(jj + bn) * D_MODEL + kk + bk8];
            float4 b1 = *(const float4*)&W[(size_t)(jj + bn) * D_MODEL + kk + bk8 + 4];
            Bs[bk8 + 0][bn] = b0.x; Bs[bk8 + 1][bn] = b0.y;
            Bs[bk8 + 2][bn] = b0.z; Bs[bk8 + 3][bn] = b0.w;
            Bs[bk8 + 4][bn] = b1.x; Bs[bk8 + 5][bn] = b1.y;
            Bs[bk8 + 6][bn] = b1.z; Bs[bk8 + 7][bn] = b1.w;
        }
        __syncthreads();
#pragma unroll
        for (int k = 0; k < 16; ++k) {
            float a[8], b[8];
            *(float4*)&a[0] = *(const float4*)&As[k][ty * 8];
            *(float4*)&a[4] = *(const float4*)&As[k][ty * 8 + 4];
            *(float4*)&b[0] = *(const float4*)&Bs[k][tx * 8];
            *(float4*)&b[4] = *(const float4*)&Bs[k][tx * 8 + 4];
#pragma unroll
            for (int i = 0; i < 8; ++i)
#pragma unroll
                for (int j = 0; j < 8; ++j)
                    acc[i][j] += a[i] * b[j];
        }
        __syncthreads();
    }
    // epilogue: add emb[tok_t] and store
#pragma unroll
    for (int i = 0; i < 8; ++i) {
        int m = ii + ty * 8 + i;
        if (m < M) {
            int b = m / Tp1, t = m - b * Tp1;
            int tok = (t == 0) ? BOS : ids[b * T + t - 1];
            const float* e = &emb[(size_t)tok * D_MODEL + jj + tx * 8];
            float4 e0 = *(const float4*)&e[0];
            float4 e1 = *(const float4*)&e[4];
            float* dst = &out[(size_t)m * D_MODEL + jj + tx * 8];
            *(float4*)&dst[0] = make_float4(acc[i][0] + e0.x, acc[i][1] + e0.y,
                                            acc[i][2] + e0.z, acc[i][3] + e0.w);
            *(float4*)&dst[4] = make_float4(acc[i][4] + e1.x, acc[i][5] + e1.y,
                                            acc[i][6] + e1.z, acc[i][7] + e1.w);
        }
    }
}

// ---------------------------------------------------------------------------
// Kernel C: persistent scan over 8 chains: H_k = y + W2 @ H_{k-1}
// chain c = (b, p): H_k == h_{2k+p} of batch b. Dependency distance 8 units.
// Probe at iteration u targets unit u+2's input, which was RELEASED at the end
// of iteration u-6 -> 6 iterations of slack hide the release->visible latency.
// ---------------------------------------------------------------------------
__global__ void __launch_bounds__(NTHREADS, 1)
rnn_scan_kernel(float* __restrict__ out, int Tp1) {
    __shared__ float4 hsm[2][D_MODEL / 4];

    const int tid  = threadIdx.x;
    const int w    = tid >> 5;
    const int lane = tid & 31;
    const int row  = blockIdx.x * 8 + w;

    // W2 row -> registers
    const float4* __restrict__ Wv = reinterpret_cast<const float4*>(g_W2);
    float4 wr[8];
#pragma unroll
    for (int k = 0; k < 8; ++k) wr[k] = Wv[(size_t)row * 256 + lane + 32 * k];

    hsm[0][tid] = make_float4(0.f, 0.f, 0.f, 0.f);   // H_{-1} = 0 for unit 0
    __syncthreads();

    const float4* hbufv = reinterpret_cast<const float4*>(g_hbuf); // [2][8][256]
    const int KMAX = (Tp1 + 1) >> 1;
    const unsigned nunits = (unsigned)KMAX * NCHAIN;

    for (unsigned u = 0; u < nunits; ++u) {
        const int k = (int)(u >> 3);
        const int c = (int)(u & 7);
        const int b = c >> 1, p = c & 1;
        const int t = 2 * k + p;
        const int q = (int)(u & 1);
        const bool valid = (t < Tp1);

        // ---- A. issue tag probe for unit u+2's input (warp 7, split txn) ----
        const unsigned u2 = u + 2;
        uint4 probe = make_uint4(~0u, ~0u, ~0u, ~0u);
        const uint4* tagp = nullptr;
        unsigned need = 0;
        if (w == 7 && u2 < nunits) {
            const int k2 = (int)(u2 >> 3), c2 = (int)(u2 & 7);
            if (k2 > 0) {
                tagp = reinterpret_cast<const uint4*>(g_tag + c2 * NCTA) + lane;
                need = (unsigned)k2;
                probe = ld_acquire_v4(tagp);
            }
        }

        // ---- B. issue h-stage load for unit u+1 (confirmed by probe at u-1) --
        const unsigned un = u + 1;
        const bool have_next = (un < nunits);
        float4 hstage;
        if (have_next) {
            const int kn = (int)(un >> 3), cn = (int)(un & 7);
            const int slot = (kn + 1) & 1;               // H_{kn-1} lives here
            hstage = __ldcg(&hbufv[((size_t)slot * NCHAIN + cn) * 256 + tid]);
        }

        // ---- y read for this unit (split txn, lane 0) ----
        float yv = 0.0f;
        size_t oidx = 0;
        if (lane == 0 && valid) {
            oidx = ((size_t)b * Tp1 + t) * D_MODEL + row;
            yv = __ldcg(&out[oidx]);
        }

        // ---- C. matvec: full row per warp, 4 accumulators ----
        const float4* __restrict__ h4 = hsm[q];
        float a0 = 0.f, a1 = 0.f, a2 = 0.f, a3 = 0.f;
#pragma unroll
        for (int kk = 0; kk < 8; kk += 4) {
            float4 h0 = h4[lane + 32 * (kk + 0)];
            float4 h1 = h4[lane + 32 * (kk + 1)];
            float4 h2 = h4[lane + 32 * (kk + 2)];
            float4 h3 = h4[lane + 32 * (kk + 3)];
            a0 += wr[kk + 0].x * h0.x; a0 += wr[kk + 0].y * h0.y;
            a0 += wr[kk + 0].z * h0.z; a0 += wr[kk + 0].w * h0.w;
            a1 += wr[kk + 1].x * h1.x; a1 += wr[kk + 1].y * h1.y;
            a1 += wr[kk + 1].z * h1.z; a1 += wr[kk + 1].w * h1.w;
            a2 += wr[kk + 2].x * h2.x; a2 += wr[kk + 2].y * h2.y;
            a2 += wr[kk + 2].z * h2.z; a2 += wr[kk + 2].w * h2.w;
            a3 += wr[kk + 3].x * h3.x; a3 += wr[kk + 3].y * h3.y;
            a3 += wr[kk + 3].z * h3.z; a3 += wr[kk + 3].w * h3.w;
        }
        float a = (a0 + a1) + (a2 + a3);
#pragma unroll
        for (int off = 16; off > 0; off >>= 1)
            a += __shfl_xor_sync(0xffffffffu, a, off);

        // ---- D. epilogue: H_k = y + W2 H_{k-1}; publish to gmem ----
        if (lane == 0 && valid) {
            float v = a + yv;
            __stcg(&g_hbuf[k & 1][c][row], v);
            out[oidx] = v;                       // overwrite y with h
        }

        // ---- E. publish stage into the other smem buffer ----
        if (have_next) hsm[q ^ 1][tid] = hstage;

        // ---- F. check probe; retry only on a genuine miss ----
        if (tagp) {
            unsigned m = min(min(probe.x, probe.y), min(probe.z, probe.w));
            while (!__all_sync(0xffffffffu, m >= need)) {
                uint4 v = ld_acquire_v4(tagp);
                m = min(min(v.x, v.y), min(v.z, v.w));
            }
        }

        // ---- G. single barrier; H. release tag ----
        __syncthreads();
        if (tid == 0) st_release_u32(&g_tag[c * NCTA + blockIdx.x], (unsigned)(k + 1));
    }
}

extern "C" void kernel_launch(void* const* d_in, const int* in_sizes, int n_in,
                              void* d_out, int out_size) {
    const int*   ids = (const int*)d_in[0];
    const float* emb = (const float*)d_in[1];
    const float* W   = (const float*)d_in[2];
    float* out = (float*)d_out;

    int Tp1 = out_size / (NB * D_MODEL);   // 2049 for the reference shapes
    int M = NB * Tp1;

    rnn_init_kernel<<<64, 256>>>();
    w2_gemm_kernel<<<dim3(8, 8), 256>>>(W);
    y_gemm_kernel<<<dim3(8, (M + 127) / 128), 256>>>(ids, emb, W, out, Tp1);
    rnn_scan_kernel<<<NCTA, NTHREADS>>>(out, Tp1);
}

// round 8
// speedup vs baseline: 2.4489x; 2.0351x over previous
#include <cuda_runtime.h>
#include <cstdint>

#define D_MODEL 1024
#define NB 4
#define NCTA 128
#define NTHREADS 256          // 8 warps, one row per warp
#define TP1_MAX 2049
#define BOS 0

typedef unsigned long long u64;

// Tagged hidden state: one 64-bit word per element = {tag:32 | value_bits:32}.
// Producer of h_t stores tag = t+1 in the SAME 8-byte scalar relaxed-atomic
// store as the value -> a consumer that sees the right tag has the right value
// (scalar naturally-aligned relaxed atomics are single-copy atomic; the v2.f32
// pair of R7 was NOT and tore). Double-buffered by t&1: overwrite distance is
// 8 units, data dependency bounds cross-CTA skew to 4 units.
__device__ u64 g_hbuf2[2][NB][D_MODEL];

__global__ void rnn_init_kernel() {
    int i = blockIdx.x * blockDim.x + threadIdx.x;
    if (i < 2 * NB * D_MODEL)
        reinterpret_cast<u64*>(g_hbuf2)[i] = 0ull;   // tag 0 == h_{-1}
}

__device__ __forceinline__ u64 ld_relaxed_u64(const u64* p) {
    u64 v;
    asm volatile("ld.relaxed.gpu.global.u64 %0, [%1];" : "=l"(v) : "l"(p) : "memory");
    return v;
}
__device__ __forceinline__ void st_relaxed_u64(u64* p, u64 v) {
    asm volatile("st.relaxed.gpu.global.u64 [%0], %1;" :: "l"(p), "l"(v) : "memory");
}

// Persistent kernel: 128 CTAs x 8 rows (one row per warp, W row in registers).
// Units (t, b), 4 interleaved batch chains, dependency distance 4 units.
// Sync protocol: the tagged data itself + one __syncthreads per unit.
__global__ void __launch_bounds__(NTHREADS, 1)
rnn_scan_kernel(const int*   __restrict__ ids,
                const float* __restrict__ emb,
                const float* __restrict__ W,
                float*       __restrict__ out,
                int Tp1)
{
    __shared__ int    ids_sm[NB * TP1_MAX];     // tokens incl. BOS
    __shared__ float4 hsm[2][D_MODEL / 4];      // staged h (one unit), dbl-buf

    const int tid  = threadIdx.x;
    const int w    = tid >> 5;
    const int lane = tid & 31;
    const int row  = blockIdx.x * 8 + w;

    // ---- W row -> registers: 32 floats/lane ----
    const float4* __restrict__ Wv = reinterpret_cast<const float4*>(W);
    float4 wr[8];
#pragma unroll
    for (int k = 0; k < 8; ++k) wr[k] = Wv[(size_t)row * 256 + lane + 32 * k];

    // ---- stage token ids with BOS prepended ----
    const int T = Tp1 - 1;
    for (int i = tid; i < NB * Tp1; i += NTHREADS) {
        int b = i / Tp1;
        int t = i - b * Tp1;
        ids_sm[i] = (t == 0) ? BOS : ids[b * T + (t - 1)];
    }
    hsm[0][tid] = make_float4(0.f, 0.f, 0.f, 0.f);   // input of unit 0 (h_{-1}=0)
    __syncthreads();

    // ---- embedding prefetch (lane0): statically-indexed per chain ----
    float e_pref[NB];
    if (lane == 0) {
#pragma unroll
        for (int b = 0; b < NB; ++b)
            e_pref[b] = emb[(size_t)ids_sm[b * Tp1] * D_MODEL + row];
    }

    for (int t = 0; t < Tp1; ++t) {
#pragma unroll
        for (int b = 0; b < NB; ++b) {
            const int q = b & 1;                     // (4t+b)&1, compile-time

            // ---- B. issue tagged stage loads for the NEXT unit's input ----
            // next unit: (t, b+1) for b<3, else (t+1, 0)
            const int  bn  = (b < 3) ? b + 1 : 0;
            const int  tn  = (b < 3) ? t : t + 1;
            const bool have_next = (b < 3) || (t + 1 < Tp1);
            const u64* sp = nullptr;
            u64 u0, u1, u2, u3;
            unsigned exp = 0;
            if (have_next) {
                const int slot = (tn + 1) & 1;       // h_{tn-1} lives here
                sp  = &g_hbuf2[slot][bn][4 * tid];
                exp = (unsigned)tn;                  // tag of h_{tn-1}
                u0 = ld_relaxed_u64(sp + 0);
                u1 = ld_relaxed_u64(sp + 1);
                u2 = ld_relaxed_u64(sp + 2);
                u3 = ld_relaxed_u64(sp + 3);
            }

            // ---- C. matvec: full row per warp, 4 accumulators ----
            const float4* __restrict__ h4 = hsm[q];
            float a0 = 0.f, a1 = 0.f, a2 = 0.f, a3 = 0.f;
#pragma unroll
            for (int kk = 0; kk < 8; kk += 4) {
                float4 h0 = h4[lane + 32 * (kk + 0)];
                float4 h1 = h4[lane + 32 * (kk + 1)];
                float4 h2 = h4[lane + 32 * (kk + 2)];
                float4 h3 = h4[lane + 32 * (kk + 3)];
                a0 += wr[kk + 0].x * h0.x; a0 += wr[kk + 0].y * h0.y;
                a0 += wr[kk + 0].z * h0.z; a0 += wr[kk + 0].w * h0.w;
                a1 += wr[kk + 1].x * h1.x; a1 += wr[kk + 1].y * h1.y;
                a1 += wr[kk + 1].z * h1.z; a1 += wr[kk + 1].w * h1.w;
                a2 += wr[kk + 2].x * h2.x; a2 += wr[kk + 2].y * h2.y;
                a2 += wr[kk + 2].z * h2.z; a2 += wr[kk + 2].w * h2.w;
                a3 += wr[kk + 3].x * h3.x; a3 += wr[kk + 3].y * h3.y;
                a3 += wr[kk + 3].z * h3.z; a3 += wr[kk + 3].w * h3.w;
            }
            float a = (a0 + a1) + (a2 + a3);
#pragma unroll
            for (int off = 16; off > 0; off >>= 1)
                a += __shfl_xor_sync(0xffffffffu, a, off);

            // ---- D. epilogue: h_t = dot + emb; tagged publish (one u64) ----
            if (lane == 0) {
                float v = a + e_pref[b];
                st_relaxed_u64(&g_hbuf2[t & 1][b][row],
                               ((u64)(unsigned)(t + 1) << 32) |
                               (u64)__float_as_uint(v));
                out[((size_t)b * Tp1 + t) * D_MODEL + row] = v;
                if (t + 1 < Tp1)   // prefetch for (t+1, b), consumed 4 units later
                    e_pref[b] = emb[(size_t)ids_sm[b * Tp1 + t + 1] * D_MODEL + row];
            }

            // ---- E. tag check (the ONLY wait) + publish stage to smem ----
            if (have_next) {
                while ((unsigned)(u0 >> 32) != exp || (unsigned)(u1 >> 32) != exp ||
                       (unsigned)(u2 >> 32) != exp || (unsigned)(u3 >> 32) != exp) {
                    u0 = ld_relaxed_u64(sp + 0);
                    u1 = ld_relaxed_u64(sp + 1);
                    u2 = ld_relaxed_u64(sp + 2);
                    u3 = ld_relaxed_u64(sp + 3);
                }
                hsm[q ^ 1][tid] = make_float4(__uint_as_float((unsigned)u0),
                                              __uint_as_float((unsigned)u1),
                                              __uint_as_float((unsigned)u2),
                                              __uint_as_float((unsigned)u3));
            }

            // ---- G. single barrier per unit ----
            __syncthreads();
        }
    }
}

extern "C" void kernel_launch(void* const* d_in, const int* in_sizes, int n_in,
                              void* d_out, int out_size) {
    const int*   ids = (const int*)d_in[0];
    const float* emb = (const float*)d_in[1];
    const float* W   = (const float*)d_in[2];
    float* out = (float*)d_out;

    int Tp1 = out_size / (NB * D_MODEL);   // 2049 for the reference shapes
    if (Tp1 > TP1_MAX) Tp1 = TP1_MAX;

    rnn_init_kernel<<<32, 256>>>();
    rnn_scan_kernel<<<NCTA, NTHREADS>>>(ids, emb, W, out, Tp1);
}